// round 16
// baseline (speedup 1.0000x reference)
#include <cuda_runtime.h>
#include <cuda_fp16.h>
#include <math.h>
#include <stdint.h>

#define BTOT 131072
#define NBLK 2048            // k1 blocks (64 rows each)

extern __shared__ char dsm[];

__device__ __forceinline__ uint32_t smem_u32(const void* p) {
    uint32_t a;
    asm("{ .reg .u64 t; cvta.to.shared.u64 t, %1; cvt.u32.u64 %0, t; }" : "=r"(a) : "l"(p));
    return a;
}
#define LDSM4(r,a) asm volatile("ldmatrix.sync.aligned.m8n8.x4.shared.b16 {%0,%1,%2,%3},[%4];" \
    : "=r"((r)[0]),"=r"((r)[1]),"=r"((r)[2]),"=r"((r)[3]) : "r"(a))
#define LDSM2(r,a) asm volatile("ldmatrix.sync.aligned.m8n8.x2.shared.b16 {%0,%1},[%2];" \
    : "=r"((r)[0]),"=r"((r)[1]) : "r"(a))
#define MMAF16(c,a,b) asm volatile( \
    "mma.sync.aligned.m16n8k16.row.col.f32.f16.f16.f32 {%0,%1,%2,%3},{%4,%5,%6,%7},{%8,%9},{%0,%1,%2,%3};" \
    : "+f"((c)[0]),"+f"((c)[1]),"+f"((c)[2]),"+f"((c)[3]) \
    : "r"((a)[0]),"r"((a)[1]),"r"((a)[2]),"r"((a)[3]),"r"((b)[0]),"r"((b)[1]))
#define CP16(dst,src) asm volatile("cp.async.cg.shared.global [%0], [%1], 16;" ::"r"(dst),"l"(src))
#define CPCOMMIT()    asm volatile("cp.async.commit_group;" ::: "memory")
#define CPWAIT0()     asm volatile("cp.async.wait_group 0;" ::: "memory")

__device__ __forceinline__ void split2h(float x0, float x1, uint32_t& h, uint32_t& l) {
    __half h0 = __float2half_rn(x0), h1 = __float2half_rn(x1);
    h = (uint32_t)__half_as_ushort(h0) | ((uint32_t)__half_as_ushort(h1) << 16);
    __half l0 = __float2half_rn(x0 - __half2float(h0));
    __half l1 = __float2half_rn(x1 - __half2float(h1));
    l = (uint32_t)__half_as_ushort(l0) | ((uint32_t)__half_as_ushort(l1) << 16);
}
__device__ __forceinline__ uint32_t packh(float x0, float x1) {
    __half h0 = __float2half_rn(x0), h1 = __float2half_rn(x1);
    return (uint32_t)__half_as_ushort(h0) | ((uint32_t)__half_as_ushort(h1) << 16);
}
// K=128 tile: 256B rows, xor swizzle -> conflict-free ldmatrix
__device__ __forceinline__ uint32_t off128(uint32_t row, uint32_t c16) {
    return row * 256u + (((c16 ^ row) & 15u) << 4);
}

// ---------- scratch ----------
__device__ __align__(16) uint32_t g_Xh2[(size_t)BTOT * 32];
__device__ __align__(16) uint32_t g_Xl2[(size_t)BTOT * 32];
__device__ float g_psum[NBLK * 64];
__device__ float g_pcov[(size_t)NBLK * 4096];
__device__ float g_pcov2[32 * 4096];
__device__ float g_pcovF[4096];
__device__ float g_bv2[64], g_bm2[64];
__device__ __align__(16) __half g_Cvh[4096], g_Cmh[4096];
__device__ __align__(16) __half g_Wc[320 * 768];
__device__ __align__(16) __half g_W2[64 * 256];
__device__ __align__(16) __half g_Wo[64 * 64];

// k1 smem layout (bytes)
#define G1_A(buf)  ((buf) * 16384)                // 64x128 fp16, 2 bufs -> 32768
#define G1_B(buf)  (32768 + (buf) * 81920)        // 320x128 fp16 -> ends 196608
// float regions (after GEMM1 dead)
#define F_HS 0            // hs [64][257] fp32 -> bytes 0..65792
#define F_HL 0            // hl [64][65] (after hs dead) bytes 0..16640
#define F_OS 4160         // os [64][65] float idx (bytes 16640..33280)
#define F_RS 16448        // rs [64][65] float idx (bytes 65792..82432)
// GELU h/l tiles + W2 tile, stride 528 B
#define GH  82432         // [64][264] fp16 = 33792
#define GL  116224
#define GW  150016        // W2 tile [64][264] -> ends 183808
// Wo / Xt tiles, stride 144 B (reuse GH region after W2)
#define OA2_H 82432
#define OA2_L 91648
#define OB2   100864
#define SM1   196608

__global__ void k0_prep(const float* __restrict__ W1, const float* __restrict__ Wr,
                        const float* __restrict__ W2, const float* __restrict__ Wo) {
    int gt = blockIdx.x * 256 + threadIdx.x, np = gridDim.x * 256;
    for (int i = gt; i < 320 * 768; i += np) {
        int r = i / 768, c = i - r * 768;
        float v = (r < 256) ? W1[r * 768 + c] : Wr[(r - 256) * 768 + c];
        g_Wc[i] = __float2half_rn(v);
    }
    for (int i = gt; i < 64 * 256; i += np) g_W2[i] = __float2half_rn(W2[i]);
    for (int i = gt; i < 4096; i += np)     g_Wo[i] = __float2half_rn(Wo[i]);
}

// ===================== k1: 64 rows/CTA, 512 threads =====================
__global__ void __launch_bounds__(512, 1)
k1_main(const float* __restrict__ z,  const float* __restrict__ b1,
        const float* __restrict__ lng, const float* __restrict__ lnb,
        const float* __restrict__ b2,  const float* __restrict__ br)
{
    char* sm = dsm;
    const uint32_t sb = smem_u32(sm);
    float* smf = (float*)sm;
    float* hs = smf + F_HS;      // [64][257]
    float* rs = smf + F_RS;      // [64][65]
    float* hl = smf + F_HL;      // [64][65] (after hs dead)
    float* os = smf + F_OS;      // [64][65]

    const int tid = threadIdx.x, wid = tid >> 5, lane = tid & 31;
    const int m0 = blockIdx.x * 64;
    const int wr = wid & 3, wc = wid >> 2;
    const int g = lane >> 2, tig = lane & 3;

    // 144-stride lane offsets (Wo / cov)
    const uint32_t aoff  = (uint32_t)(lane & 15) * 144u + (uint32_t)((lane >> 4) * 16);
    const uint32_t boff4 = (uint32_t)(((lane >> 4) & 1) * 8 + (lane & 7)) * 144u
                         + (uint32_t)(((lane >> 3) & 1) * 16);
    const uint32_t aRow = (uint32_t)(wr * 16) * 144u;
    // 528-stride lane offsets (W2 via GELU tiles)
    const uint32_t aoff5 = (uint32_t)(wr * 16 + (lane & 15)) * 528u + (uint32_t)((lane >> 4) * 16);
    const uint32_t boff5 = (uint32_t)(wc * 16 + ((lane >> 4) & 1) * 8 + (lane & 7)) * 528u
                         + (uint32_t)(((lane >> 3) & 1) * 16);
    const int blocal = ((lane >> 4) & 1) * 8 + (lane & 7);
    const int bhalf  = (lane >> 3) & 1;

    // ---- GEMM1: 64 x 320 x 768, fp16 A 1-term, K=128 chunks (6 iters) ----
    float acc[10][4];
    #pragma unroll
    for (int j = 0; j < 10; j++) { acc[j][0]=0.f; acc[j][1]=0.f; acc[j][2]=0.f; acc[j][3]=0.f; }

    const int arow = tid >> 3, aq = tid & 7;   // 16 floats per thread per chunk
    const float* zp = z + (size_t)(m0 + arow) * 768 + aq * 16;
    const uint32_t aS0 = off128((uint32_t)arow, (uint32_t)(aq * 2));
    const uint32_t aS1 = off128((uint32_t)arow, (uint32_t)(aq * 2 + 1));
    uint32_t bdst[10]; int bsrc[10];
    #pragma unroll
    for (int it = 0; it < 10; it++) {
        int u = tid + it * 512, row = u >> 4, c16 = u & 15;
        bdst[it] = off128((uint32_t)row, (uint32_t)c16);
        bsrc[it] = row * 768 + c16 * 8;
    }
    #pragma unroll
    for (int it = 0; it < 10; it++) CP16(sb + G1_B(0) + bdst[it], g_Wc + bsrc[it]);
    CPCOMMIT();
    float4 a0 = *(const float4*)(zp);
    float4 a1 = *(const float4*)(zp + 4);
    float4 a2 = *(const float4*)(zp + 8);
    float4 a3 = *(const float4*)(zp + 12);

    for (int ch = 0; ch < 6; ch++) {
        const int cur = ch & 1;
        *(uint4*)(sm + G1_A(cur) + aS0) = make_uint4(packh(a0.x, a0.y), packh(a0.z, a0.w),
                                                     packh(a1.x, a1.y), packh(a1.z, a1.w));
        *(uint4*)(sm + G1_A(cur) + aS1) = make_uint4(packh(a2.x, a2.y), packh(a2.z, a2.w),
                                                     packh(a3.x, a3.y), packh(a3.z, a3.w));
        if (ch < 5) {
            const float* zn = zp + (ch + 1) * 128;
            a0 = *(const float4*)(zn);
            a1 = *(const float4*)(zn + 4);
            a2 = *(const float4*)(zn + 8);
            a3 = *(const float4*)(zn + 12);
        }
        CPWAIT0();
        __syncthreads();
        if (ch < 5) {
            const int kk = (ch + 1) * 128, nb = cur ^ 1;
            #pragma unroll
            for (int it = 0; it < 10; it++) CP16(sb + G1_B(nb) + bdst[it], g_Wc + bsrc[it] + kk);
            CPCOMMIT();
        }
        const uint32_t Ah = sb + G1_A(cur), Bh = sb + G1_B(cur);
        #pragma unroll
        for (int ks = 0; ks < 8; ks++) {
            uint32_t ah[4];
            LDSM4(ah, Ah + off128((uint32_t)(wr * 16 + (lane & 15)), (uint32_t)(ks * 2 + (lane >> 4))));
            uint32_t bb[5][4];
            #pragma unroll
            for (int q = 0; q < 5; q++)
                LDSM4(bb[q], Bh + off128((uint32_t)(wc * 80 + q * 16 + blocal),
                                         (uint32_t)(ks * 2 + bhalf)));
            #pragma unroll
            for (int q = 0; q < 5; q++) {
                MMAF16(acc[2*q],   ah, bb[q]);
                MMAF16(acc[2*q+1], ah, bb[q] + 2);
            }
        }
    }
    __syncthreads();

    // scatter acc -> hs (+b1) / rs (+br)
    #pragma unroll
    for (int j = 0; j < 10; j++) {
        int col = wc * 80 + j * 8 + tig * 2;
        int r0 = wr * 16 + g, r1 = r0 + 8;
        #pragma unroll
        for (int e = 0; e < 2; e++) {
            int c = col + e;
            float v0 = acc[j][e], v1 = acc[j][2 + e];
            if (c < 256) {
                hs[r0 * 257 + c] = v0 + __ldg(&b1[c]);
                hs[r1 * 257 + c] = v1 + __ldg(&b1[c]);
            } else {
                rs[r0 * 65 + c - 256] = v0 + __ldg(&br[c - 256]);
                rs[r1 * 65 + c - 256] = v1 + __ldg(&br[c - 256]);
            }
        }
    }
    // W2 weight tile load (independent of hs) - overlap with scatter
    #pragma unroll
    for (int it = 0; it < 4; it++) {
        int u = tid + it * 512, row = u >> 5, c16 = u & 31;
        *(uint4*)(sm + GW + (uint32_t)row * 528u + (uint32_t)c16 * 16u)
            = *(const uint4*)(g_W2 + (size_t)row * 256 + c16 * 8);
    }
    __syncthreads();

    // ---- LayerNorm + exact GELU -> fp16 h/l tiles (528-stride) ----
    for (int rr = wid; rr < 64; rr += 16) {
        float v[8], s = 0.f, s2 = 0.f;
        #pragma unroll
        for (int j = 0; j < 8; j++) {
            float x = hs[rr * 257 + lane + 32 * j];
            v[j] = x; s += x; s2 += x * x;
        }
        #pragma unroll
        for (int o = 16; o > 0; o >>= 1) {
            s  += __shfl_xor_sync(~0u, s,  o);
            s2 += __shfl_xor_sync(~0u, s2, o);
        }
        float mean = s * (1.f / 256.f);
        float rstd = rsqrtf(s2 * (1.f / 256.f) - mean * mean + 1e-5f);
        #pragma unroll
        for (int j = 0; j < 8; j++) {
            int c = lane + 32 * j;
            float y = (v[j] - mean) * rstd * __ldg(&lng[c]) + __ldg(&lnb[c]);
            float gv = 0.5f * y * (1.0f + erff(y * 0.70710678118654752f));
            __half hb = __float2half_rn(gv);
            *(__half*)(sm + GH + rr * 528 + c * 2) = hb;
            *(__half*)(sm + GL + rr * 528 + c * 2) = __float2half_rn(gv - __half2float(hb));
        }
    }
    __syncthreads();

    // ---- W2 GEMM: 64 x 64 x 256, single uninterrupted 16-ks loop ----
    float acc2[2][4];
    acc2[0][0]=0.f; acc2[0][1]=0.f; acc2[0][2]=0.f; acc2[0][3]=0.f;
    acc2[1][0]=0.f; acc2[1][1]=0.f; acc2[1][2]=0.f; acc2[1][3]=0.f;
    #pragma unroll
    for (int ks = 0; ks < 16; ks++) {
        const uint32_t ka = (uint32_t)ks * 32u;
        uint32_t ah[4], al[4], b0[4];
        LDSM4(ah, sb + GH + aoff5 + ka);
        LDSM4(al, sb + GL + aoff5 + ka);
        LDSM4(b0, sb + GW + boff5 + ka);
        MMAF16(acc2[0], ah, b0); MMAF16(acc2[1], ah, b0 + 2);
        MMAF16(acc2[0], al, b0); MMAF16(acc2[1], al, b0 + 2);
    }
    __syncthreads();   // hs fully consumed (LN done); hl/os region writable
    #pragma unroll
    for (int j = 0; j < 2; j++) {
        int col = wc * 16 + j * 8 + tig * 2;
        int r0 = wr * 16 + g, r1 = r0 + 8;
        #pragma unroll
        for (int e = 0; e < 2; e++) {
            int c = col + e;
            hl[r0 * 65 + c] = acc2[j][e]     + __ldg(&b2[c]) + rs[r0 * 65 + c];
            hl[r1 * 65 + c] = acc2[j][2 + e] + __ldg(&b2[c]) + rs[r1 * 65 + c];
        }
    }
    __syncthreads();

    // ---- Wo GEMM: tiles at 144-stride (reuse GH region) ----
    #pragma unroll
    for (int it = 0; it < 4; it++) {
        int p = tid + it * 512, row = p >> 5, cp = p & 31;
        if (p < 2048) {
            uint32_t h01, l01;
            split2h(hl[row * 65 + 2 * cp], hl[row * 65 + 2 * cp + 1], h01, l01);
            uint32_t off = (uint32_t)row * 144u + (uint32_t)cp * 4u;
            *(uint32_t*)(sm + OA2_H + off) = h01;
            *(uint32_t*)(sm + OA2_L + off) = l01;
        }
    }
    {
        int row = tid >> 3, c = tid & 7;
        *(uint4*)(sm + OB2 + (uint32_t)row * 144u + (uint32_t)c * 16u) = *(const uint4*)(g_Wo + (size_t)row * 64 + c * 8);
    }
    __syncthreads();
    float acc3[2][4];
    acc3[0][0]=0.f; acc3[0][1]=0.f; acc3[0][2]=0.f; acc3[0][3]=0.f;
    acc3[1][0]=0.f; acc3[1][1]=0.f; acc3[1][2]=0.f; acc3[1][3]=0.f;
    #pragma unroll
    for (int ks = 0; ks < 4; ks++) {
        const uint32_t ka = (uint32_t)ks * 32u;
        uint32_t ah[4], al[4], b0[4];
        LDSM4(ah, sb + OA2_H + aRow + aoff + ka);
        LDSM4(al, sb + OA2_L + aRow + aoff + ka);
        LDSM4(b0, sb + OB2 + (uint32_t)(wc * 16) * 144u + boff4 + ka);
        MMAF16(acc3[0], ah, b0); MMAF16(acc3[1], ah, b0 + 2);
        MMAF16(acc3[0], al, b0); MMAF16(acc3[1], al, b0 + 2);
    }
    __syncthreads();

    // os + Xt
    #pragma unroll
    for (int j = 0; j < 2; j++) {
        int col = wc * 16 + j * 8 + tig * 2;
        int r0 = wr * 16 + g, r1 = r0 + 8;
        #pragma unroll
        for (int e = 0; e < 2; e++) {
            int c = col + e;
            float v0 = acc3[j][e], v1 = acc3[j][2 + e];
            os[r0 * 65 + c] = v0;
            os[r1 * 65 + c] = v1;
            __half hb0 = __float2half_rn(v0);
            __half hb1 = __float2half_rn(v1);
            *(__half*)(sm + OA2_H + c * 144 + r0 * 2) = hb0;
            *(__half*)(sm + OA2_H + c * 144 + r1 * 2) = hb1;
            *(__half*)(sm + OA2_L + c * 144 + r0 * 2) = __float2half_rn(v0 - __half2float(hb0));
            *(__half*)(sm + OA2_L + c * 144 + r1 * 2) = __float2half_rn(v1 - __half2float(hb1));
        }
    }
    __syncthreads();

    // cov
    float acc4[2][4];
    acc4[0][0]=0.f; acc4[0][1]=0.f; acc4[0][2]=0.f; acc4[0][3]=0.f;
    acc4[1][0]=0.f; acc4[1][1]=0.f; acc4[1][2]=0.f; acc4[1][3]=0.f;
    #pragma unroll
    for (int ks = 0; ks < 4; ks++) {
        const uint32_t ka = (uint32_t)ks * 32u;
        uint32_t ah[4], al[4], b0[4];
        LDSM4(ah, sb + OA2_H + aRow + aoff + ka);
        LDSM4(al, sb + OA2_L + aRow + aoff + ka);
        LDSM4(b0, sb + OA2_H + (uint32_t)(wc * 16) * 144u + boff4 + ka);
        MMAF16(acc4[0], ah, b0); MMAF16(acc4[1], ah, b0 + 2);
        MMAF16(acc4[0], al, b0); MMAF16(acc4[1], al, b0 + 2);
    }
    {
        float* pc = g_pcov + (size_t)blockIdx.x * 4096;
        int j1a = wr * 16 + g, j1b = j1a + 8;
        #pragma unroll
        for (int j = 0; j < 2; j++) {
            int j2 = wc * 16 + j * 8 + tig * 2;
            *(float2*)(pc + j1a * 64 + j2) = make_float2(acc4[j][0], acc4[j][1]);
            *(float2*)(pc + j1b * 64 + j2) = make_float2(acc4[j][2], acc4[j][3]);
        }
    }

    // X store as packed fp16 h/l pairs
    #pragma unroll
    for (int it = 0; it < 4; it++) {
        int i = tid + it * 512;
        int row = i >> 5, cp = i & 31;
        float x0 = os[row * 65 + 2 * cp], x1 = os[row * 65 + 2 * cp + 1];
        uint32_t h01, l01;
        split2h(x0, x1, h01, l01);
        g_Xh2[(size_t)(m0 + row) * 32 + cp] = h01;
        g_Xl2[(size_t)(m0 + row) * 32 + cp] = l01;
    }
    // psum: parallel (rs dead)
    {
        int col = tid & 63, grp = tid >> 6;
        float s = 0.f;
        #pragma unroll
        for (int r = 0; r < 8; r++) s += os[(grp * 8 + r) * 65 + col];
        rs[grp * 64 + col] = s;
    }
    __syncthreads();
    if (tid < 64) {
        float s = 0.f;
        #pragma unroll
        for (int g2 = 0; g2 < 8; g2++) s += rs[g2 * 64 + tid];
        g_psum[blockIdx.x * 64 + tid] = s;
    }
}

__global__ void k_red() {
    int gt = blockIdx.x * 256 + threadIdx.x;
    int e = gt & 4095, ch = gt >> 12;
    const float* p = g_pcov + (size_t)ch * 64 * 4096 + e;
    float s = 0.f;
    #pragma unroll 8
    for (int b = 0; b < 64; b++) s += p[(size_t)b * 4096];
    g_pcov2[ch * 4096 + e] = s;
}
__global__ void k_red2() {
    int e = blockIdx.x * 256 + threadIdx.x;
    float s = 0.f;
    #pragma unroll
    for (int c = 0; c < 32; c++) s += g_pcov2[c * 4096 + e];
    g_pcovF[e] = s;
}

// ===================== k2: tensor-core Newton-Schulz =====================
#define K2_SSH 0
#define K2_SSL 9216
#define K2_WAH 18432
#define K2_WAL 27648
#define K2_WBH 36864
#define K2_WBL 46080
#define K2_TH  55296
#define K2_TL  64512
#define K2_PH  73728
#define K2_PL  82944
#define K2_F32 92160
#define SM2    110592

__device__ __forceinline__ void t_mm(char* sm, uint32_t sb,
    uint32_t Ah, uint32_t Al, uint32_t Bh, uint32_t Bl,
    uint32_t Oh, uint32_t Ol, int mode, uint32_t WoH, uint32_t WoL,
    int wm, int wn, int lane)
{
    const uint32_t ao = (uint32_t)(wm * 16 + (lane & 15)) * 144u + (uint32_t)((lane >> 4) * 16);
    const uint32_t bo = (uint32_t)(wn * 8 + (lane & 7)) * 144u + (uint32_t)(((lane >> 3) & 1) * 16);
    float c[4] = {0.f, 0.f, 0.f, 0.f};
    #pragma unroll
    for (int ks = 0; ks < 4; ks++) {
        const uint32_t ka = (uint32_t)ks * 32u;
        uint32_t ah[4], al[4], bh[2], bl[2];
        LDSM4(ah, sb + Ah + ao + ka);
        LDSM4(al, sb + Al + ao + ka);
        LDSM2(bh, sb + Bh + bo + ka);
        LDSM2(bl, sb + Bl + bo + ka);
        MMAF16(c, ah, bh);
        MMAF16(c, al, bh);
        MMAF16(c, ah, bl);
    }
    const int r0 = wm * 16 + (lane >> 2), r1 = r0 + 8;
    const int j0 = wn * 8 + (lane & 3) * 2;
    if (mode) {
        #pragma unroll
        for (int e = 0; e < 2; e++) {
            int rr = e ? r1 : r0;
            float w0 = __half2float(*(__half*)(sm + WoH + rr * 144 + j0 * 2))
                     + __half2float(*(__half*)(sm + WoL + rr * 144 + j0 * 2));
            float w1 = __half2float(*(__half*)(sm + WoH + rr * 144 + j0 * 2 + 2))
                     + __half2float(*(__half*)(sm + WoL + rr * 144 + j0 * 2 + 2));
            c[2*e]   = 1.5f * w0 - 0.5f * c[2*e];
            c[2*e+1] = 1.5f * w1 - 0.5f * c[2*e+1];
        }
    }
    uint32_t h01, l01;
    split2h(c[0], c[1], h01, l01);
    *(uint32_t*)(sm + Oh + r0 * 144 + j0 * 2) = h01;
    *(uint32_t*)(sm + Ol + r0 * 144 + j0 * 2) = l01;
    split2h(c[2], c[3], h01, l01);
    *(uint32_t*)(sm + Oh + r1 * 144 + j0 * 2) = h01;
    *(uint32_t*)(sm + Ol + r1 * 144 + j0 * 2) = l01;
}

__global__ void __launch_bounds__(1024)
k2_ns(const float* __restrict__ Wv, const float* __restrict__ bv,
      const float* __restrict__ Wm, const float* __restrict__ bm)
{
    char* sm = dsm;
    const uint32_t sb = smem_u32(sm);
    float* Wf  = (float*)(sm + K2_F32);
    float* Cvf = (float*)(sm + K2_PH);
    float* Cmf = (float*)(sm + K2_TH);
    __shared__ float mu[64]; __shared__ float sn_s;
    const int tid = threadIdx.x, wid = tid >> 5, lane = tid & 31;
    const int wm = wid & 3, wn = wid >> 2;
    const float Bf = (float)BTOT;
    const int j = tid & 63, rb = (tid >> 6) * 4;

    {
        int col = tid & 63, q = tid >> 6;
        float s = 0.f;
        for (int b = q; b < NBLK; b += 16) s += g_psum[b * 64 + col];
        Wf[q * 64 + col] = s;
        __syncthreads();
        if (tid < 64) {
            float t = 0.f;
            #pragma unroll
            for (int q2 = 0; q2 < 16; q2++) t += Wf[q2 * 64 + tid];
            mu[tid] = t / Bf;
        }
        __syncthreads();
    }
    for (int i = tid; i < 4096; i += 1024) {
        int j1 = i >> 6, j2 = i & 63;
        float sig = (g_pcovF[i] - Bf * mu[j1] * mu[j2]) / (Bf - 1.0f);
        if (j1 == j2) sig += 0.001f;
        Wf[j1 * 68 + j2] = sig;
    }
    __syncthreads();
    if (tid < 32) {
        float t = Wf[tid * 68 + tid] + Wf[(tid + 32) * 68 + tid + 32];
        #pragma unroll
        for (int o = 16; o > 0; o >>= 1) t += __shfl_xor_sync(~0u, t, o);
        if (tid == 0) sn_s = t * 1.5f + 1e-6f;
    }
    __syncthreads();
    const float sn = sn_s;
    for (int i = tid; i < 4096; i += 1024) {
        int r = i >> 6, c = i & 63;
        float v = Wf[r * 68 + c] / sn;
        __half hb = __float2half_rn(v);
        *(__half*)(sm + K2_SSH + r * 144 + c * 2) = hb;
        *(__half*)(sm + K2_SSL + r * 144 + c * 2) = __float2half_rn(v - __half2float(hb));
        *(__half*)(sm + K2_WAH + r * 144 + c * 2) = __float2half_rn((r == c) ? 1.f : 0.f);
        *(__half*)(sm + K2_WAL + r * 144 + c * 2) = __float2half_rn(0.f);
    }
    __syncthreads();

    uint32_t WaH = K2_WAH, WaL = K2_WAL, WbH = K2_WBH, WbL = K2_WBL;
    for (int it = 0; it < 5; it++) {
        t_mm(sm, sb, WaH, WaL, K2_SSH, K2_SSL, K2_TH, K2_TL, 0, 0, 0, wm, wn, lane);
        __syncthreads();
        t_mm(sm, sb, K2_TH, K2_TL, WaH, WaL, K2_PH, K2_PL, 0, 0, 0, wm, wn, lane);
        __syncthreads();
        t_mm(sm, sb, K2_PH, K2_PL, WaH, WaL, WbH, WbL, 1, WaH, WaL, wm, wn, lane);
        __syncthreads();
        uint32_t th = WaH; WaH = WbH; WbH = th;
        uint32_t tl = WaL; WaL = WbL; WbL = tl;
    }

    for (int i = tid; i < 4096; i += 1024) {
        int r = i >> 6, c = i & 63;
        Wf[r * 68 + c] = __half2float(*(__half*)(sm + WaH + r * 144 + c * 2))
                       + __half2float(*(__half*)(sm + WaL + r * 144 + c * 2));
    }
    __syncthreads();

    const float iss = rsqrtf(sn);
    {
        float sv[4] = {0,0,0,0}, smk[4] = {0,0,0,0};
        #pragma unroll
        for (int k4 = 0; k4 < 16; k4++) {
            float4 bb = *(float4*)&Wf[j * 68 + k4 * 4];
            #pragma unroll
            for (int i = 0; i < 4; i++) {
                float4 av = __ldg((const float4*)(Wv + (rb + i) * 64 + k4 * 4));
                float4 am = __ldg((const float4*)(Wm + (rb + i) * 64 + k4 * 4));
                sv[i]  += av.x*bb.x + av.y*bb.y + av.z*bb.z + av.w*bb.w;
                smk[i] += am.x*bb.x + am.y*bb.y + am.z*bb.z + am.w*bb.w;
            }
        }
        #pragma unroll
        for (int i = 0; i < 4; i++) {
            int jr = rb + i;
            float cv = sv[i] * iss, cm = smk[i] * iss;
            g_Cvh[jr * 64 + j] = __float2half_rn(cv);
            g_Cmh[jr * 64 + j] = __float2half_rn(cm);
            Cvf[jr * 68 + j] = cv;
            Cmf[jr * 68 + j] = cm;
        }
    }
    __syncthreads();
    if (tid < 64) {
        float s = 0.f, t = 0.f;
        #pragma unroll 8
        for (int k = 0; k < 64; k++) { s += mu[k] * Cvf[tid * 68 + k]; t += mu[k] * Cmf[tid * 68 + k]; }
        g_bv2[tid] = bv[tid] - s;
        g_bm2[tid] = bm[tid] - t;
    }
}

// k3: 128 rows/block; X tiles pre-split, Cv/Cm pre-rounded fp16
#define K3_XH 0
#define K3_XL 18432
#define K3_VH 36864
#define K3_MH 46080
#define SM3   55296
__global__ void __launch_bounds__(256)
k3_out(float* __restrict__ out, const float* __restrict__ scale)
{
    char* sm = dsm;
    const uint32_t sb = smem_u32(sm);
    const int tid = threadIdx.x, wid = tid >> 5, lane = tid & 31;
    const int m0 = blockIdx.x * 128;
    const int wr = wid & 3, wc = wid >> 2;
    const int g = lane >> 2, tig = lane & 3;
    const uint32_t aoff  = (uint32_t)(lane & 15) * 144u + (uint32_t)((lane >> 4) * 16);
    const uint32_t boff4 = (uint32_t)(((lane >> 4) & 1) * 8 + (lane & 7)) * 144u
                         + (uint32_t)(((lane >> 3) & 1) * 16);

    {
        int row = tid >> 1, q = tid & 1;
        const uint4* ph = (const uint4*)(g_Xh2 + (size_t)(m0 + row) * 32 + q * 16);
        const uint4* pl = (const uint4*)(g_Xl2 + (size_t)(m0 + row) * 32 + q * 16);
        uint32_t off = (uint32_t)row * 144u + (uint32_t)q * 64u;
        #pragma unroll
        for (int f = 0; f < 4; f++) {
            *(uint4*)(sm + K3_XH + off + f * 16) = __ldg(ph + f);
            *(uint4*)(sm + K3_XL + off + f * 16) = __ldg(pl + f);
        }
    }
    {
        int row = tid >> 2, q = tid & 3;
        uint32_t off = (uint32_t)row * 144u + (uint32_t)q * 32u;
        const uint4* vp = (const uint4*)(g_Cvh + row * 64 + q * 16);
        const uint4* mp = (const uint4*)(g_Cmh + row * 64 + q * 16);
        *(uint4*)(sm + K3_VH + off)      = __ldg(vp);
        *(uint4*)(sm + K3_VH + off + 16) = __ldg(vp + 1);
        *(uint4*)(sm + K3_MH + off)      = __ldg(mp);
        *(uint4*)(sm + K3_MH + off + 16) = __ldg(mp + 1);
    }
    __syncthreads();

    float av[2][4][4], am[2][4][4];
    #pragma unroll
    for (int mi = 0; mi < 2; mi++)
        #pragma unroll
        for (int jj = 0; jj < 4; jj++)
            #pragma unroll
            for (int q = 0; q < 4; q++) { av[mi][jj][q] = 0.f; am[mi][jj][q] = 0.f; }
    #pragma unroll
    for (int ks = 0; ks < 4; ks++) {
        const uint32_t ka = (uint32_t)ks * 32u;
        uint32_t ah0[4], al0[4], ah1[4], al1[4];
        LDSM4(ah0, sb + K3_XH + (uint32_t)(wr * 16) * 144u + aoff + ka);
        LDSM4(al0, sb + K3_XL + (uint32_t)(wr * 16) * 144u + aoff + ka);
        LDSM4(ah1, sb + K3_XH + (uint32_t)(64 + wr * 16) * 144u + aoff + ka);
        LDSM4(al1, sb + K3_XL + (uint32_t)(64 + wr * 16) * 144u + aoff + ka);
        uint32_t vb0[4], vb1[4], mb0[4], mb1[4];
        const uint32_t br0 = (uint32_t)(wc * 32)      * 144u + boff4 + ka;
        const uint32_t br1 = (uint32_t)(wc * 32 + 16) * 144u + boff4 + ka;
        LDSM4(vb0, sb + K3_VH + br0); LDSM4(vb1, sb + K3_VH + br1);
        LDSM4(mb0, sb + K3_MH + br0); LDSM4(mb1, sb + K3_MH + br1);
        MMAF16(av[0][0], ah0, vb0); MMAF16(av[0][1], ah0, vb0 + 2);
        MMAF16(av[0][2], ah0, vb1); MMAF16(av[0][3], ah0, vb1 + 2);
        MMAF16(am[0][0], ah0, mb0); MMAF16(am[0][1], ah0, mb0 + 2);
        MMAF16(am[0][2], ah0, mb1); MMAF16(am[0][3], ah0, mb1 + 2);
        MMAF16(av[1][0], ah1, vb0); MMAF16(av[1][1], ah1, vb0 + 2);
        MMAF16(av[1][2], ah1, vb1); MMAF16(av[1][3], ah1, vb1 + 2);
        MMAF16(am[1][0], ah1, mb0); MMAF16(am[1][1], ah1, mb0 + 2);
        MMAF16(am[1][2], ah1, mb1); MMAF16(am[1][3], ah1, mb1 + 2);
        MMAF16(av[0][0], al0, vb0); MMAF16(av[0][1], al0, vb0 + 2);
        MMAF16(av[0][2], al0, vb1); MMAF16(av[0][3], al0, vb1 + 2);
        MMAF16(am[0][0], al0, mb0); MMAF16(am[0][1], al0, mb0 + 2);
        MMAF16(am[0][2], al0, mb1); MMAF16(am[0][3], al0, mb1 + 2);
        MMAF16(av[1][0], al1, vb0); MMAF16(av[1][1], al1, vb0 + 2);
        MMAF16(av[1][2], al1, vb1); MMAF16(av[1][3], al1, vb1 + 2);
        MMAF16(am[1][0], al1, mb0); MMAF16(am[1][1], al1, mb0 + 2);
        MMAF16(am[1][2], al1, mb1); MMAF16(am[1][3], al1, mb1 + 2);
    }
    const float sc = __ldg(scale);
    #pragma unroll
    for (int mi = 0; mi < 2; mi++) {
        int r0 = mi * 64 + wr * 16 + g, r1 = r0 + 8;
        #pragma unroll
        for (int jj = 0; jj < 4; jj++) {
            int c = wc * 32 + jj * 8 + tig * 2;
            float bvc0 = __ldg(&g_bv2[c]), bvc1 = __ldg(&g_bv2[c + 1]);
            float bmc0 = __ldg(&g_bm2[c]), bmc1 = __ldg(&g_bm2[c + 1]);
            float o00 = (av[mi][jj][0] + bvc0) * sc / (1.f + expf(-(am[mi][jj][0] + bmc0)));
            float o01 = (av[mi][jj][1] + bvc1) * sc / (1.f + expf(-(am[mi][jj][1] + bmc1)));
            float o10 = (av[mi][jj][2] + bvc0) * sc / (1.f + expf(-(am[mi][jj][2] + bmc0)));
            float o11 = (av[mi][jj][3] + bvc1) * sc / (1.f + expf(-(am[mi][jj][3] + bmc1)));
            *(float2*)(out + (size_t)(m0 + r0) * 64 + c) = make_float2(o00, o01);
            *(float2*)(out + (size_t)(m0 + r1) * 64 + c) = make_float2(o10, o11);
        }
    }
}

extern "C" void kernel_launch(void* const* d_in, const int* in_sizes, int n_in,
                              void* d_out, int out_size)
{
    (void)in_sizes; (void)n_in; (void)out_size;
    const float* z  = (const float*)d_in[0];
    const float* W1 = (const float*)d_in[1];
    const float* b1 = (const float*)d_in[2];
    const float* lg = (const float*)d_in[3];
    const float* lb = (const float*)d_in[4];
    const float* W2 = (const float*)d_in[5];
    const float* b2 = (const float*)d_in[6];
    const float* Wr = (const float*)d_in[7];
    const float* br = (const float*)d_in[8];
    const float* Wo = (const float*)d_in[9];
    const float* Wv = (const float*)d_in[10];
    const float* bv = (const float*)d_in[11];
    const float* Wm = (const float*)d_in[12];
    const float* bm = (const float*)d_in[13];
    const float* sc = (const float*)d_in[14];
    float* out = (float*)d_out;

    cudaFuncSetAttribute(k1_main, cudaFuncAttributeMaxDynamicSharedMemorySize, SM1);
    cudaFuncSetAttribute(k2_ns,  cudaFuncAttributeMaxDynamicSharedMemorySize, SM2);
    cudaFuncSetAttribute(k3_out, cudaFuncAttributeMaxDynamicSharedMemorySize, SM3);

    k0_prep<<<256, 256>>>(W1, Wr, W2, Wo);
    k1_main<<<NBLK, 512, SM1>>>(z, b1, lg, lb, b2, br);
    k_red<<<512, 256>>>();
    k_red2<<<16, 256>>>();
    k2_ns<<<1, 1024, SM2>>>(Wv, bv, Wm, bm);
    k3_out<<<1024, 256, SM3>>>(out, sc);
}

// round 17
// speedup vs baseline: 1.1028x; 1.1028x over previous
#include <cuda_runtime.h>
#include <cuda_fp16.h>
#include <math.h>
#include <stdint.h>

#define BTOT 131072
#define NBLK 2048            // k1 blocks (64 rows each)

extern __shared__ char dsm[];

__device__ __forceinline__ uint32_t smem_u32(const void* p) {
    uint32_t a;
    asm("{ .reg .u64 t; cvta.to.shared.u64 t, %1; cvt.u32.u64 %0, t; }" : "=r"(a) : "l"(p));
    return a;
}
#define LDSM4(r,a) asm volatile("ldmatrix.sync.aligned.m8n8.x4.shared.b16 {%0,%1,%2,%3},[%4];" \
    : "=r"((r)[0]),"=r"((r)[1]),"=r"((r)[2]),"=r"((r)[3]) : "r"(a))
#define LDSM2(r,a) asm volatile("ldmatrix.sync.aligned.m8n8.x2.shared.b16 {%0,%1},[%2];" \
    : "=r"((r)[0]),"=r"((r)[1]) : "r"(a))
#define MMAF16(c,a,b) asm volatile( \
    "mma.sync.aligned.m16n8k16.row.col.f32.f16.f16.f32 {%0,%1,%2,%3},{%4,%5,%6,%7},{%8,%9},{%0,%1,%2,%3};" \
    : "+f"((c)[0]),"+f"((c)[1]),"+f"((c)[2]),"+f"((c)[3]) \
    : "r"((a)[0]),"r"((a)[1]),"r"((a)[2]),"r"((a)[3]),"r"((b)[0]),"r"((b)[1]))
#define CP16(dst,src) asm volatile("cp.async.cg.shared.global [%0], [%1], 16;" ::"r"(dst),"l"(src))
#define CPCOMMIT()    asm volatile("cp.async.commit_group;" ::: "memory")
#define CPWAIT0()     asm volatile("cp.async.wait_group 0;" ::: "memory")

__device__ __forceinline__ void split2h(float x0, float x1, uint32_t& h, uint32_t& l) {
    __half h0 = __float2half_rn(x0), h1 = __float2half_rn(x1);
    h = (uint32_t)__half_as_ushort(h0) | ((uint32_t)__half_as_ushort(h1) << 16);
    __half l0 = __float2half_rn(x0 - __half2float(h0));
    __half l1 = __float2half_rn(x1 - __half2float(h1));
    l = (uint32_t)__half_as_ushort(l0) | ((uint32_t)__half_as_ushort(l1) << 16);
}
__device__ __forceinline__ uint32_t packh(float x0, float x1) {
    __half h0 = __float2half_rn(x0), h1 = __float2half_rn(x1);
    return (uint32_t)__half_as_ushort(h0) | ((uint32_t)__half_as_ushort(h1) << 16);
}
// K=32 tile: 64B rows, rotation swizzle -> conflict-free ldmatrix
__device__ __forceinline__ uint32_t off32(uint32_t row, uint32_t c16) {
    return row * 64u + (((c16 + (row >> 1)) & 3u) << 4);
}

// ---------- scratch ----------
__device__ float g_X[(size_t)BTOT * 64];
__device__ float g_psum[NBLK * 64];
__device__ float g_pcov[(size_t)NBLK * 4096];
__device__ float g_pcov2[32 * 4096];
__device__ float g_pcovF[4096];
__device__ float g_bv2[64], g_bm2[64];
__device__ __align__(16) __half g_Cvh[4096], g_Cmh[4096];
__device__ __align__(16) __half g_Wc[320 * 768];
__device__ __align__(16) __half g_W2[64 * 256];
__device__ __align__(16) __half g_Wo[64 * 64];

// k1 smem layout (bytes) — fits 2 CTAs/SM
#define G1_A(buf)  ((buf) * 4096)               // 64x32 fp16 -> 8192
#define G1_B(buf)  (8192 + (buf) * 20480)       // 320x32 fp16 -> ends 49152
#define F_HS 0            // hs [64][257] fp32: bytes 0..65792
#define F_RS 16448        // rs [64][65]: bytes 65792..82432
#define F_HL 0            // hl [64][65] (aliases dead hs): bytes 0..16640
#define F_OS 4160         // os [64][65]: bytes 16640..33280
#define OA2_H 82432
#define OA2_L 91648
#define OB2   100864      // ends 110080
#define SM1   110592

__global__ void k0_prep(const float* __restrict__ W1, const float* __restrict__ Wr,
                        const float* __restrict__ W2, const float* __restrict__ Wo) {
    int gt = blockIdx.x * 256 + threadIdx.x, np = gridDim.x * 256;
    for (int i = gt; i < 320 * 768; i += np) {
        int r = i / 768, c = i - r * 768;
        float v = (r < 256) ? W1[r * 768 + c] : Wr[(r - 256) * 768 + c];
        g_Wc[i] = __float2half_rn(v);
    }
    for (int i = gt; i < 64 * 256; i += np) g_W2[i] = __float2half_rn(W2[i]);
    for (int i = gt; i < 4096; i += np)     g_Wo[i] = __float2half_rn(Wo[i]);
}

// ===================== k1: 64 rows/CTA, 256 threads, 2 CTAs/SM =====================
__global__ void __launch_bounds__(256, 2)
k1_main(const float* __restrict__ z,  const float* __restrict__ b1,
        const float* __restrict__ lng, const float* __restrict__ lnb,
        const float* __restrict__ b2,  const float* __restrict__ br)
{
    char* sm = dsm;
    const uint32_t sb = smem_u32(sm);
    float* smf = (float*)sm;
    float* hs = smf + F_HS;      // [64][257]
    float* rs = smf + F_RS;      // [64][65]
    float* hl = smf + F_HL;      // [64][65] (aliases dead hs)
    float* os = smf + F_OS;      // [64][65]

    const int tid = threadIdx.x, wid = tid >> 5, lane = tid & 31;
    const int m0 = blockIdx.x * 64;
    const int wr = wid & 3, wc = wid >> 2;          // 4 x 2 warp grid
    const int g = lane >> 2, tig = lane & 3;

    const uint32_t aoff  = (uint32_t)(lane & 15) * 144u + (uint32_t)((lane >> 4) * 16);
    const uint32_t boff4 = (uint32_t)(((lane >> 4) & 1) * 8 + (lane & 7)) * 144u
                         + (uint32_t)(((lane >> 3) & 1) * 16);
    const uint32_t aRow = (uint32_t)(wr * 16) * 144u;
    const int blocal = ((lane >> 4) & 1) * 8 + (lane & 7);
    const int bhalf  = (lane >> 3) & 1;

    // ---- GEMM1: 64 x 320 x 768, fp16 A 1-term, K=32 chunks (24 iters) ----
    float acc[20][4];
    #pragma unroll
    for (int j = 0; j < 20; j++) { acc[j][0]=0.f; acc[j][1]=0.f; acc[j][2]=0.f; acc[j][3]=0.f; }

    const int arow = tid >> 2, ac16 = tid & 3;
    const float* zp = z + (size_t)(m0 + arow) * 768 + ac16 * 8;
    const uint32_t aSts = off32((uint32_t)arow, (uint32_t)ac16);
    // B addresses recomputed inline (saves registers)
    #pragma unroll
    for (int it = 0; it < 5; it++) {
        int u = tid + it * 256, row = u >> 2, c16 = u & 3;
        CP16(sb + G1_B(0) + off32((uint32_t)row, (uint32_t)c16), g_Wc + row * 768 + c16 * 8);
    }
    CPCOMMIT();
    float4 a0 = *(const float4*)(zp);
    float4 a1 = *(const float4*)(zp + 4);

    for (int ch = 0; ch < 24; ch++) {
        const int cur = ch & 1;
        *(uint4*)(sm + G1_A(cur) + aSts) = make_uint4(packh(a0.x, a0.y), packh(a0.z, a0.w),
                                                      packh(a1.x, a1.y), packh(a1.z, a1.w));
        float4 n0 = a0, n1 = a1;
        if (ch < 23) {
            n0 = *(const float4*)(zp + (ch + 1) * 32);
            n1 = *(const float4*)(zp + (ch + 1) * 32 + 4);
        }
        CPWAIT0();
        __syncthreads();
        if (ch < 23) {
            const int kk = (ch + 1) * 32, nb = cur ^ 1;
            #pragma unroll
            for (int it = 0; it < 5; it++) {
                int u = tid + it * 256, row = u >> 2, c16 = u & 3;
                CP16(sb + G1_B(nb) + off32((uint32_t)row, (uint32_t)c16), g_Wc + row * 768 + kk + c16 * 8);
            }
            CPCOMMIT();
        }
        const uint32_t Ah = sb + G1_A(cur), Bh = sb + G1_B(cur);
        #pragma unroll
        for (int ks = 0; ks < 2; ks++) {
            uint32_t ah[4];
            LDSM4(ah, Ah + off32((uint32_t)(wr * 16 + (lane & 15)), (uint32_t)(ks * 2 + (lane >> 4))));
            #pragma unroll
            for (int pg = 0; pg < 2; pg++) {
                uint32_t bb[5][4];
                #pragma unroll
                for (int q = 0; q < 5; q++) {
                    int p = pg * 5 + q;
                    LDSM4(bb[q], Bh + off32((uint32_t)(wc * 160 + p * 16 + blocal),
                                            (uint32_t)(ks * 2 + bhalf)));
                }
                #pragma unroll
                for (int q = 0; q < 5; q++) {
                    int p = pg * 5 + q;
                    MMAF16(acc[2*p],   ah, bb[q]);
                    MMAF16(acc[2*p+1], ah, bb[q] + 2);
                }
            }
        }
        a0 = n0; a1 = n1;
    }
    __syncthreads();

    // scatter acc -> hs (+b1) / rs (+br)
    #pragma unroll
    for (int j = 0; j < 20; j++) {
        int col = wc * 160 + j * 8 + tig * 2;
        int r0 = wr * 16 + g, r1 = r0 + 8;
        #pragma unroll
        for (int e = 0; e < 2; e++) {
            int c = col + e;
            float v0 = acc[j][e], v1 = acc[j][2 + e];
            if (c < 256) {
                hs[r0 * 257 + c] = v0 + __ldg(&b1[c]);
                hs[r1 * 257 + c] = v1 + __ldg(&b1[c]);
            } else {
                rs[r0 * 65 + c - 256] = v0 + __ldg(&br[c - 256]);
                rs[r1 * 65 + c - 256] = v1 + __ldg(&br[c - 256]);
            }
        }
    }
    __syncthreads();

    // ---- LayerNorm + exact GELU ----
    for (int rr = wid; rr < 64; rr += 8) {
        float v[8], s = 0.f, s2 = 0.f;
        #pragma unroll
        for (int j = 0; j < 8; j++) {
            float x = hs[rr * 257 + lane + 32 * j];
            v[j] = x; s += x; s2 += x * x;
        }
        #pragma unroll
        for (int o = 16; o > 0; o >>= 1) {
            s  += __shfl_xor_sync(~0u, s,  o);
            s2 += __shfl_xor_sync(~0u, s2, o);
        }
        float mean = s * (1.f / 256.f);
        float rstd = rsqrtf(s2 * (1.f / 256.f) - mean * mean + 1e-5f);
        #pragma unroll
        for (int j = 0; j < 8; j++) {
            int c = lane + 32 * j;
            float y = (v[j] - mean) * rstd * __ldg(&lng[c]) + __ldg(&lnb[c]);
            hs[rr * 257 + c] = 0.5f * y * (1.0f + erff(y * 0.70710678118654752f));
        }
    }
    __syncthreads();

    // ---- W2 GEMM: 64 x 64 x 256 (fp16 2-term A) ----
    float acc2[4][4];
    #pragma unroll
    for (int j = 0; j < 4; j++) { acc2[j][0]=0.f; acc2[j][1]=0.f; acc2[j][2]=0.f; acc2[j][3]=0.f; }
    for (int c2 = 0; c2 < 4; c2++) {
        const int kk2 = c2 * 64;
        #pragma unroll
        for (int it = 0; it < 8; it++) {
            int p = tid + it * 256, row = p >> 5, cp = p & 31;
            uint32_t h01, l01;
            split2h(hs[row * 257 + kk2 + 2 * cp], hs[row * 257 + kk2 + 2 * cp + 1], h01, l01);
            uint32_t off = (uint32_t)row * 144u + (uint32_t)cp * 4u;
            *(uint32_t*)(sm + OA2_H + off) = h01;
            *(uint32_t*)(sm + OA2_L + off) = l01;
        }
        #pragma unroll
        for (int it = 0; it < 2; it++) {
            int p = tid + it * 256, row = p >> 3, c = p & 7;
            size_t si = (size_t)row * 256 + kk2 + c * 8;
            *(uint4*)(sm + OB2 + (uint32_t)row * 144u + (uint32_t)c * 16u) = *(const uint4*)(g_W2 + si);
        }
        __syncthreads();
        #pragma unroll
        for (int ks = 0; ks < 4; ks++) {
            const uint32_t ka = (uint32_t)ks * 32u;
            uint32_t ah[4], al[4], b0[4], b1r[4];
            LDSM4(ah, sb + OA2_H + aRow + aoff + ka);
            LDSM4(al, sb + OA2_L + aRow + aoff + ka);
            LDSM4(b0,  sb + OB2 + (uint32_t)(wc * 32)      * 144u + boff4 + ka);
            LDSM4(b1r, sb + OB2 + (uint32_t)(wc * 32 + 16) * 144u + boff4 + ka);
            MMAF16(acc2[0], ah, b0);  MMAF16(acc2[1], ah, b0 + 2);
            MMAF16(acc2[2], ah, b1r); MMAF16(acc2[3], ah, b1r + 2);
            MMAF16(acc2[0], al, b0);  MMAF16(acc2[1], al, b0 + 2);
            MMAF16(acc2[2], al, b1r); MMAF16(acc2[3], al, b1r + 2);
        }
        __syncthreads();
    }
    #pragma unroll
    for (int j = 0; j < 4; j++) {
        int col = wc * 32 + j * 8 + tig * 2;
        int r0 = wr * 16 + g, r1 = r0 + 8;
        #pragma unroll
        for (int e = 0; e < 2; e++) {
            int c = col + e;
            hl[r0 * 65 + c] = acc2[j][e]     + __ldg(&b2[c]) + rs[r0 * 65 + c];
            hl[r1 * 65 + c] = acc2[j][2 + e] + __ldg(&b2[c]) + rs[r1 * 65 + c];
        }
    }
    __syncthreads();

    // ---- Wo GEMM ----
    #pragma unroll
    for (int it = 0; it < 8; it++) {
        int p = tid + it * 256, row = p >> 5, cp = p & 31;
        uint32_t h01, l01;
        split2h(hl[row * 65 + 2 * cp], hl[row * 65 + 2 * cp + 1], h01, l01);
        uint32_t off = (uint32_t)row * 144u + (uint32_t)cp * 4u;
        *(uint32_t*)(sm + OA2_H + off) = h01;
        *(uint32_t*)(sm + OA2_L + off) = l01;
    }
    #pragma unroll
    for (int it = 0; it < 2; it++) {
        int p = tid + it * 256, row = p >> 3, c = p & 7;
        *(uint4*)(sm + OB2 + (uint32_t)row * 144u + (uint32_t)c * 16u) = *(const uint4*)(g_Wo + (size_t)row * 64 + c * 8);
    }
    __syncthreads();
    float acc3[4][4];
    #pragma unroll
    for (int j = 0; j < 4; j++) { acc3[j][0]=0.f; acc3[j][1]=0.f; acc3[j][2]=0.f; acc3[j][3]=0.f; }
    #pragma unroll
    for (int ks = 0; ks < 4; ks++) {
        const uint32_t ka = (uint32_t)ks * 32u;
        uint32_t ah[4], al[4], b0[4], b1r[4];
        LDSM4(ah, sb + OA2_H + aRow + aoff + ka);
        LDSM4(al, sb + OA2_L + aRow + aoff + ka);
        LDSM4(b0,  sb + OB2 + (uint32_t)(wc * 32)      * 144u + boff4 + ka);
        LDSM4(b1r, sb + OB2 + (uint32_t)(wc * 32 + 16) * 144u + boff4 + ka);
        MMAF16(acc3[0], ah, b0);  MMAF16(acc3[1], ah, b0 + 2);
        MMAF16(acc3[2], ah, b1r); MMAF16(acc3[3], ah, b1r + 2);
        MMAF16(acc3[0], al, b0);  MMAF16(acc3[1], al, b0 + 2);
        MMAF16(acc3[2], al, b1r); MMAF16(acc3[3], al, b1r + 2);
    }
    __syncthreads();

    // os + Xt
    #pragma unroll
    for (int j = 0; j < 4; j++) {
        int col = wc * 32 + j * 8 + tig * 2;
        int r0 = wr * 16 + g, r1 = r0 + 8;
        #pragma unroll
        for (int e = 0; e < 2; e++) {
            int c = col + e;
            float v0 = acc3[j][e], v1 = acc3[j][2 + e];
            os[r0 * 65 + c] = v0;
            os[r1 * 65 + c] = v1;
            __half hb0 = __float2half_rn(v0);
            __half hb1 = __float2half_rn(v1);
            *(__half*)(sm + OA2_H + c * 144 + r0 * 2) = hb0;
            *(__half*)(sm + OA2_H + c * 144 + r1 * 2) = hb1;
            *(__half*)(sm + OA2_L + c * 144 + r0 * 2) = __float2half_rn(v0 - __half2float(hb0));
            *(__half*)(sm + OA2_L + c * 144 + r1 * 2) = __float2half_rn(v1 - __half2float(hb1));
        }
    }
    __syncthreads();

    // cov
    float acc4[4][4];
    #pragma unroll
    for (int j = 0; j < 4; j++) { acc4[j][0]=0.f; acc4[j][1]=0.f; acc4[j][2]=0.f; acc4[j][3]=0.f; }
    #pragma unroll
    for (int ks = 0; ks < 4; ks++) {
        const uint32_t ka = (uint32_t)ks * 32u;
        uint32_t ah[4], al[4], b0[4], b1r[4];
        LDSM4(ah, sb + OA2_H + aRow + aoff + ka);
        LDSM4(al, sb + OA2_L + aRow + aoff + ka);
        LDSM4(b0,  sb + OA2_H + (uint32_t)(wc * 32)      * 144u + boff4 + ka);
        LDSM4(b1r, sb + OA2_H + (uint32_t)(wc * 32 + 16) * 144u + boff4 + ka);
        MMAF16(acc4[0], ah, b0);  MMAF16(acc4[1], ah, b0 + 2);
        MMAF16(acc4[2], ah, b1r); MMAF16(acc4[3], ah, b1r + 2);
        MMAF16(acc4[0], al, b0);  MMAF16(acc4[1], al, b0 + 2);
        MMAF16(acc4[2], al, b1r); MMAF16(acc4[3], al, b1r + 2);
    }
    {
        float* pc = g_pcov + (size_t)blockIdx.x * 4096;
        int j1a = wr * 16 + g, j1b = j1a + 8;
        #pragma unroll
        for (int j = 0; j < 4; j++) {
            int j2 = wc * 32 + j * 8 + tig * 2;
            *(float2*)(pc + j1a * 64 + j2) = make_float2(acc4[j][0], acc4[j][1]);
            *(float2*)(pc + j1b * 64 + j2) = make_float2(acc4[j][2], acc4[j][3]);
        }
    }

    // X + psum
    for (int i = tid; i < 4096; i += 256) {
        int row = i >> 6, j = i & 63;
        g_X[(size_t)(m0 + row) * 64 + j] = os[row * 65 + j];
    }
    {
        int col = tid & 63, grp = tid >> 6;   // 4 groups x 16 rows
        float s = 0.f;
        #pragma unroll
        for (int r = 0; r < 16; r++) s += os[(grp * 16 + r) * 65 + col];
        rs[grp * 64 + col] = s;
    }
    __syncthreads();
    if (tid < 64) {
        float s = rs[tid] + rs[64 + tid] + rs[128 + tid] + rs[192 + tid];
        g_psum[blockIdx.x * 64 + tid] = s;
    }
}

__global__ void k_red() {
    int gt = blockIdx.x * 256 + threadIdx.x;
    int e = gt & 4095, ch = gt >> 12;
    const float* p = g_pcov + (size_t)ch * 64 * 4096 + e;
    float s = 0.f;
    #pragma unroll 8
    for (int b = 0; b < 64; b++) s += p[(size_t)b * 4096];
    g_pcov2[ch * 4096 + e] = s;
}
__global__ void k_red2() {
    int e = blockIdx.x * 256 + threadIdx.x;
    float s = 0.f;
    #pragma unroll
    for (int c = 0; c < 32; c++) s += g_pcov2[c * 4096 + e];
    g_pcovF[e] = s;
}

// ===================== k2: tensor-core Newton-Schulz (R14) =====================
#define K2_SSH 0
#define K2_SSL 9216
#define K2_WAH 18432
#define K2_WAL 27648
#define K2_WBH 36864
#define K2_WBL 46080
#define K2_TH  55296
#define K2_TL  64512
#define K2_PH  73728
#define K2_PL  82944
#define K2_F32 92160
#define SM2    110592

__device__ __forceinline__ void t_mm(char* sm, uint32_t sb,
    uint32_t Ah, uint32_t Al, uint32_t Bh, uint32_t Bl,
    uint32_t Oh, uint32_t Ol, int mode, uint32_t WoH, uint32_t WoL,
    int wm, int wn, int lane)
{
    const uint32_t ao = (uint32_t)(wm * 16 + (lane & 15)) * 144u + (uint32_t)((lane >> 4) * 16);
    const uint32_t bo = (uint32_t)(wn * 8 + (lane & 7)) * 144u + (uint32_t)(((lane >> 3) & 1) * 16);
    float c[4] = {0.f, 0.f, 0.f, 0.f};
    #pragma unroll
    for (int ks = 0; ks < 4; ks++) {
        const uint32_t ka = (uint32_t)ks * 32u;
        uint32_t ah[4], al[4], bh[2], bl[2];
        LDSM4(ah, sb + Ah + ao + ka);
        LDSM4(al, sb + Al + ao + ka);
        LDSM2(bh, sb + Bh + bo + ka);
        LDSM2(bl, sb + Bl + bo + ka);
        MMAF16(c, ah, bh);
        MMAF16(c, al, bh);
        MMAF16(c, ah, bl);
    }
    const int r0 = wm * 16 + (lane >> 2), r1 = r0 + 8;
    const int j0 = wn * 8 + (lane & 3) * 2;
    if (mode) {
        #pragma unroll
        for (int e = 0; e < 2; e++) {
            int rr = e ? r1 : r0;
            float w0 = __half2float(*(__half*)(sm + WoH + rr * 144 + j0 * 2))
                     + __half2float(*(__half*)(sm + WoL + rr * 144 + j0 * 2));
            float w1 = __half2float(*(__half*)(sm + WoH + rr * 144 + j0 * 2 + 2))
                     + __half2float(*(__half*)(sm + WoL + rr * 144 + j0 * 2 + 2));
            c[2*e]   = 1.5f * w0 - 0.5f * c[2*e];
            c[2*e+1] = 1.5f * w1 - 0.5f * c[2*e+1];
        }
    }
    uint32_t h01, l01;
    split2h(c[0], c[1], h01, l01);
    *(uint32_t*)(sm + Oh + r0 * 144 + j0 * 2) = h01;
    *(uint32_t*)(sm + Ol + r0 * 144 + j0 * 2) = l01;
    split2h(c[2], c[3], h01, l01);
    *(uint32_t*)(sm + Oh + r1 * 144 + j0 * 2) = h01;
    *(uint32_t*)(sm + Ol + r1 * 144 + j0 * 2) = l01;
}

__global__ void __launch_bounds__(1024)
k2_ns(const float* __restrict__ Wv, const float* __restrict__ bv,
      const float* __restrict__ Wm, const float* __restrict__ bm)
{
    char* sm = dsm;
    const uint32_t sb = smem_u32(sm);
    float* Wf  = (float*)(sm + K2_F32);
    float* Cvf = (float*)(sm + K2_PH);
    float* Cmf = (float*)(sm + K2_TH);
    __shared__ float mu[64]; __shared__ float sn_s;
    const int tid = threadIdx.x, wid = tid >> 5, lane = tid & 31;
    const int wm = wid & 3, wn = wid >> 2;
    const float Bf = (float)BTOT;
    const int j = tid & 63, rb = (tid >> 6) * 4;

    {
        int col = tid & 63, q = tid >> 6;
        float s = 0.f;
        for (int b = q; b < NBLK; b += 16) s += g_psum[b * 64 + col];
        Wf[q * 64 + col] = s;
        __syncthreads();
        if (tid < 64) {
            float t = 0.f;
            #pragma unroll
            for (int q2 = 0; q2 < 16; q2++) t += Wf[q2 * 64 + tid];
            mu[tid] = t / Bf;
        }
        __syncthreads();
    }
    for (int i = tid; i < 4096; i += 1024) {
        int j1 = i >> 6, j2 = i & 63;
        float sig = (g_pcovF[i] - Bf * mu[j1] * mu[j2]) / (Bf - 1.0f);
        if (j1 == j2) sig += 0.001f;
        Wf[j1 * 68 + j2] = sig;
    }
    __syncthreads();
    if (tid < 32) {
        float t = Wf[tid * 68 + tid] + Wf[(tid + 32) * 68 + tid + 32];
        #pragma unroll
        for (int o = 16; o > 0; o >>= 1) t += __shfl_xor_sync(~0u, t, o);
        if (tid == 0) sn_s = t * 1.5f + 1e-6f;
    }
    __syncthreads();
    const float sn = sn_s;
    for (int i = tid; i < 4096; i += 1024) {
        int r = i >> 6, c = i & 63;
        float v = Wf[r * 68 + c] / sn;
        __half hb = __float2half_rn(v);
        *(__half*)(sm + K2_SSH + r * 144 + c * 2) = hb;
        *(__half*)(sm + K2_SSL + r * 144 + c * 2) = __float2half_rn(v - __half2float(hb));
        *(__half*)(sm + K2_WAH + r * 144 + c * 2) = __float2half_rn((r == c) ? 1.f : 0.f);
        *(__half*)(sm + K2_WAL + r * 144 + c * 2) = __float2half_rn(0.f);
    }
    __syncthreads();

    uint32_t WaH = K2_WAH, WaL = K2_WAL, WbH = K2_WBH, WbL = K2_WBL;
    for (int it = 0; it < 5; it++) {
        t_mm(sm, sb, WaH, WaL, K2_SSH, K2_SSL, K2_TH, K2_TL, 0, 0, 0, wm, wn, lane);
        __syncthreads();
        t_mm(sm, sb, K2_TH, K2_TL, WaH, WaL, K2_PH, K2_PL, 0, 0, 0, wm, wn, lane);
        __syncthreads();
        t_mm(sm, sb, K2_PH, K2_PL, WaH, WaL, WbH, WbL, 1, WaH, WaL, wm, wn, lane);
        __syncthreads();
        uint32_t th = WaH; WaH = WbH; WbH = th;
        uint32_t tl = WaL; WaL = WbL; WbL = tl;
    }

    for (int i = tid; i < 4096; i += 1024) {
        int r = i >> 6, c = i & 63;
        Wf[r * 68 + c] = __half2float(*(__half*)(sm + WaH + r * 144 + c * 2))
                       + __half2float(*(__half*)(sm + WaL + r * 144 + c * 2));
    }
    __syncthreads();

    const float iss = rsqrtf(sn);
    {
        float sv[4] = {0,0,0,0}, smk[4] = {0,0,0,0};
        #pragma unroll
        for (int k4 = 0; k4 < 16; k4++) {
            float4 bb = *(float4*)&Wf[j * 68 + k4 * 4];
            #pragma unroll
            for (int i = 0; i < 4; i++) {
                float4 av = __ldg((const float4*)(Wv + (rb + i) * 64 + k4 * 4));
                float4 am = __ldg((const float4*)(Wm + (rb + i) * 64 + k4 * 4));
                sv[i]  += av.x*bb.x + av.y*bb.y + av.z*bb.z + av.w*bb.w;
                smk[i] += am.x*bb.x + am.y*bb.y + am.z*bb.z + am.w*bb.w;
            }
        }
        #pragma unroll
        for (int i = 0; i < 4; i++) {
            int jr = rb + i;
            float cv = sv[i] * iss, cm = smk[i] * iss;
            g_Cvh[jr * 64 + j] = __float2half_rn(cv);
            g_Cmh[jr * 64 + j] = __float2half_rn(cm);
            Cvf[jr * 68 + j] = cv;
            Cmf[jr * 68 + j] = cm;
        }
    }
    __syncthreads();
    if (tid < 64) {
        float s = 0.f, t = 0.f;
        #pragma unroll 8
        for (int k = 0; k < 64; k++) { s += mu[k] * Cvf[tid * 68 + k]; t += mu[k] * Cmf[tid * 68 + k]; }
        g_bv2[tid] = bv[tid] - s;
        g_bm2[tid] = bm[tid] - t;
    }
}

// k3: tensor epilogue (R14: 64 rows/block, X split in-kernel, Cv/Cm fp16)
#define K3_XH 0
#define K3_XL 9216
#define K3_VH 18432
#define K3_MH 27648
#define SM3   36864
__global__ void __launch_bounds__(256)
k3_out(float* __restrict__ out, const float* __restrict__ scale)
{
    char* sm = dsm;
    const uint32_t sb = smem_u32(sm);
    const int tid = threadIdx.x, wid = tid >> 5, lane = tid & 31;
    const int m0 = blockIdx.x * 64;
    const int wr = wid & 3, wc = wid >> 2;
    const int g = lane >> 2, tig = lane & 3;
    const uint32_t aoff  = (uint32_t)(lane & 15) * 144u + (uint32_t)((lane >> 4) * 16);
    const uint32_t boff4 = (uint32_t)(((lane >> 4) & 1) * 8 + (lane & 7)) * 144u
                         + (uint32_t)(((lane >> 3) & 1) * 16);
    const uint32_t aRow = (uint32_t)(wr * 16) * 144u;

    {
        int row = tid >> 2, q = tid & 3;
        uint32_t off = (uint32_t)row * 144u + (uint32_t)q * 32u;
        {
            const float* xp = g_X + (size_t)(m0 + row) * 64 + q * 16;
            uint32_t h[8], l[8];
            #pragma unroll
            for (int f = 0; f < 4; f++) {
                float4 v = __ldg((const float4*)(xp + f * 4));
                split2h(v.x, v.y, h[f*2],   l[f*2]);
                split2h(v.z, v.w, h[f*2+1], l[f*2+1]);
            }
            *(uint4*)(sm + K3_XH + off)      = make_uint4(h[0], h[1], h[2], h[3]);
            *(uint4*)(sm + K3_XH + off + 16) = make_uint4(h[4], h[5], h[6], h[7]);
            *(uint4*)(sm + K3_XL + off)      = make_uint4(l[0], l[1], l[2], l[3]);
            *(uint4*)(sm + K3_XL + off + 16) = make_uint4(l[4], l[5], l[6], l[7]);
        }
        {
            const uint4* vp = (const uint4*)(g_Cvh + row * 64 + q * 16);
            const uint4* mp = (const uint4*)(g_Cmh + row * 64 + q * 16);
            *(uint4*)(sm + K3_VH + off)      = __ldg(vp);
            *(uint4*)(sm + K3_VH + off + 16) = __ldg(vp + 1);
            *(uint4*)(sm + K3_MH + off)      = __ldg(mp);
            *(uint4*)(sm + K3_MH + off + 16) = __ldg(mp + 1);
        }
    }
    __syncthreads();

    float av[4][4], am[4][4];
    #pragma unroll
    for (int jj = 0; jj < 4; jj++)
        #pragma unroll
        for (int q = 0; q < 4; q++) { av[jj][q] = 0.f; am[jj][q] = 0.f; }
    #pragma unroll
    for (int ks = 0; ks < 4; ks++) {
        const uint32_t ka = (uint32_t)ks * 32u;
        uint32_t ah[4], al[4];
        LDSM4(ah, sb + K3_XH + aRow + aoff + ka);
        LDSM4(al, sb + K3_XL + aRow + aoff + ka);
        uint32_t vb0[4], vb1[4], mb0[4], mb1[4];
        const uint32_t br0 = (uint32_t)(wc * 32)      * 144u + boff4 + ka;
        const uint32_t br1 = (uint32_t)(wc * 32 + 16) * 144u + boff4 + ka;
        LDSM4(vb0, sb + K3_VH + br0); LDSM4(vb1, sb + K3_VH + br1);
        LDSM4(mb0, sb + K3_MH + br0); LDSM4(mb1, sb + K3_MH + br1);
        MMAF16(av[0], ah, vb0); MMAF16(av[1], ah, vb0 + 2);
        MMAF16(av[2], ah, vb1); MMAF16(av[3], ah, vb1 + 2);
        MMAF16(am[0], ah, mb0); MMAF16(am[1], ah, mb0 + 2);
        MMAF16(am[2], ah, mb1); MMAF16(am[3], ah, mb1 + 2);
        MMAF16(av[0], al, vb0); MMAF16(av[1], al, vb0 + 2);
        MMAF16(av[2], al, vb1); MMAF16(av[3], al, vb1 + 2);
        MMAF16(am[0], al, mb0); MMAF16(am[1], al, mb0 + 2);
        MMAF16(am[2], al, mb1); MMAF16(am[3], al, mb1 + 2);
    }
    const float sc = __ldg(scale);
    int r0 = wr * 16 + g, r1 = r0 + 8;
    #pragma unroll
    for (int jj = 0; jj < 4; jj++) {
        int c = wc * 32 + jj * 8 + tig * 2;
        float bvc0 = __ldg(&g_bv2[c]), bvc1 = __ldg(&g_bv2[c + 1]);
        float bmc0 = __ldg(&g_bm2[c]), bmc1 = __ldg(&g_bm2[c + 1]);
        float o00 = (av[jj][0] + bvc0) * sc / (1.f + expf(-(am[jj][0] + bmc0)));
        float o01 = (av[jj][1] + bvc1) * sc / (1.f + expf(-(am[jj][1] + bmc1)));
        float o10 = (av[jj][2] + bvc0) * sc / (1.f + expf(-(am[jj][2] + bmc0)));
        float o11 = (av[jj][3] + bvc1) * sc / (1.f + expf(-(am[jj][3] + bmc1)));
        *(float2*)(out + (size_t)(m0 + r0) * 64 + c) = make_float2(o00, o01);
        *(float2*)(out + (size_t)(m0 + r1) * 64 + c) = make_float2(o10, o11);
    }
}

extern "C" void kernel_launch(void* const* d_in, const int* in_sizes, int n_in,
                              void* d_out, int out_size)
{
    (void)in_sizes; (void)n_in; (void)out_size;
    const float* z  = (const float*)d_in[0];
    const float* W1 = (const float*)d_in[1];
    const float* b1 = (const float*)d_in[2];
    const float* lg = (const float*)d_in[3];
    const float* lb = (const float*)d_in[4];
    const float* W2 = (const float*)d_in[5];
    const float* b2 = (const float*)d_in[6];
    const float* Wr = (const float*)d_in[7];
    const float* br = (const float*)d_in[8];
    const float* Wo = (const float*)d_in[9];
    const float* Wv = (const float*)d_in[10];
    const float* bv = (const float*)d_in[11];
    const float* Wm = (const float*)d_in[12];
    const float* bm = (const float*)d_in[13];
    const float* sc = (const float*)d_in[14];
    float* out = (float*)d_out;

    cudaFuncSetAttribute(k1_main, cudaFuncAttributeMaxDynamicSharedMemorySize, SM1);
    cudaFuncSetAttribute(k2_ns,  cudaFuncAttributeMaxDynamicSharedMemorySize, SM2);
    cudaFuncSetAttribute(k3_out, cudaFuncAttributeMaxDynamicSharedMemorySize, SM3);

    k0_prep<<<256, 256>>>(W1, Wr, W2, Wo);
    k1_main<<<NBLK, 256, SM1>>>(z, b1, lg, lb, b2, br);
    k_red<<<512, 256>>>();
    k_red2<<<16, 256>>>();
    k2_ns<<<1, 1024, SM2>>>(Wv, bv, Wm, bm);
    k3_out<<<2048, 256, SM3>>>(out, sc);
}